// round 4
// baseline (speedup 1.0000x reference)
#include <cuda_runtime.h>
#include <cuda_bf16.h>
#include <math.h>

// ---------------------------------------------------------------------------
// Problem constants
// ---------------------------------------------------------------------------
#define BB 2
#define SS 2048
#define DD 1024
#define HH 16
#define FF 4096
#define LL 3
#define DK 64
#define MM (BB*SS)          // 4096 rows

// ---------------------------------------------------------------------------
// Scratch (device globals: the sanctioned alternative to cudaMalloc)
// ---------------------------------------------------------------------------
__device__ float g_x  [MM*DD];   // residual stream
__device__ float g_h  [MM*DD];   // LN output / GEMM input
__device__ float g_q  [MM*DD];
__device__ float g_k  [MM*DD];
__device__ float g_v  [MM*DD];
__device__ float g_o  [MM*DD];   // attention output
__device__ float g_mid[MM*FF];   // FFN intermediate

// ---------------------------------------------------------------------------
// Embedding + positional encoding:  x = emb[tok]*sqrt(D) + pe[s]
// ---------------------------------------------------------------------------
__global__ __launch_bounds__(256) void embed_kernel(
    const int* __restrict__ tokens, const float* __restrict__ emb,
    const float* __restrict__ pe)
{
    int idx = blockIdx.x * 256 + threadIdx.x;      // over MM*DD = 4M
    int bs  = idx >> 10;                            // row
    int d   = idx & 1023;
    int tok = tokens[bs];
    int s   = bs & (SS - 1);
    g_x[idx] = emb[tok * DD + d] * 32.0f + pe[s * DD + d];
}

// ---------------------------------------------------------------------------
// LayerNorm, torch semantics: std uses Bessel (n-1), eps added to std.
// ---------------------------------------------------------------------------
__global__ __launch_bounds__(256) void ln_kernel(
    const float* __restrict__ src, float* __restrict__ dst,
    const float* __restrict__ ga, const float* __restrict__ gb)
{
    __shared__ float red[8];
    __shared__ float bval;
    int row = blockIdx.x, tid = threadIdx.x;
    float4 v = ((const float4*)(src + row * DD))[tid];

    float s = v.x + v.y + v.z + v.w;
    #pragma unroll
    for (int off = 16; off; off >>= 1) s += __shfl_xor_sync(0xffffffffu, s, off);
    if ((tid & 31) == 0) red[tid >> 5] = s;
    __syncthreads();
    if (tid == 0) {
        float t = 0.f;
        #pragma unroll
        for (int i = 0; i < 8; i++) t += red[i];
        bval = t * (1.0f / DD);
    }
    __syncthreads();
    float mean = bval;

    float dx = v.x - mean, dy = v.y - mean, dz = v.z - mean, dw = v.w - mean;
    float sq = dx*dx + dy*dy + dz*dz + dw*dw;
    #pragma unroll
    for (int off = 16; off; off >>= 1) sq += __shfl_xor_sync(0xffffffffu, sq, off);
    if ((tid & 31) == 0) red[tid >> 5] = sq;
    __syncthreads();
    if (tid == 0) {
        float t = 0.f;
        #pragma unroll
        for (int i = 0; i < 8; i++) t += red[i];
        bval = t;
    }
    __syncthreads();
    float stdv = sqrtf(bval * (1.0f / (DD - 1)));
    float inv  = 1.0f / (stdv + 1e-6f);

    int c = tid * 4;
    float4 o;
    o.x = ga[c + 0] * dx * inv + gb[c + 0];
    o.y = ga[c + 1] * dy * inv + gb[c + 1];
    o.z = ga[c + 2] * dz * inv + gb[c + 2];
    o.w = ga[c + 3] * dw * inv + gb[c + 3];
    ((float4*)(dst + row * DD))[tid] = o;
}

// ---------------------------------------------------------------------------
// TF32 tensor-core GEMM: C[M,N] = A[M,K] @ B[K,N] + bias (+relu) (+residual)
// 128x128 block tile, 256 threads = 8 warps (2 M x 4 N), warp tile 64x32.
// k-block 16 (two m16n8k8 steps), double-buffered smem.
// Smem holds tf32 data ALREADY IN FRAGMENT ORDER so mainloop fragment
// fetches are single conflict-free lds.128 (A) / lds.64 (B).
//
// A fragment (m16n8k8, row-major): element (mm,kk) of a 16x8 tile lives at
//   lane = (mm&7)*4 + (kk&3), slot = (kk>>2)*2 + (mm>>3)   [4 slots]
// B fragment (col-major 8x8): element (kk,nn) lives at
//   lane = nn*4 + (kk&3), slot = kk>>2                     [2 slots]
// ---------------------------------------------------------------------------
__device__ __forceinline__ unsigned f2tf32(float f) {
    unsigned u;
    asm("cvt.rna.tf32.f32 %0, %1;" : "=r"(u) : "f"(f));
    return u;
}

__device__ __forceinline__ void mma_tf32(float c[4], const uint4 a, const uint2 b) {
    asm volatile(
        "mma.sync.aligned.m16n8k8.row.col.f32.tf32.tf32.f32 "
        "{%0,%1,%2,%3}, {%4,%5,%6,%7}, {%8,%9}, {%0,%1,%2,%3};\n"
        : "+f"(c[0]), "+f"(c[1]), "+f"(c[2]), "+f"(c[3])
        : "r"(a.x), "r"(a.y), "r"(a.z), "r"(a.w), "r"(b.x), "r"(b.y));
}

template<bool RELU, bool RES>
__global__ __launch_bounds__(256) void tgemm_kernel(
    const float* __restrict__ A, const float* __restrict__ B,
    const float* __restrict__ bias, const float* __restrict__ res,
    float* __restrict__ C, int M, int N, int K)
{
    __shared__ __align__(16) unsigned As[2][2048];  // [buf][ s*1024 + mt*128 + lane*4 + slot ]
    __shared__ __align__(16) unsigned Bs[2][2048];  // [buf][ s*1024 + nt*64  + lane*2 + slot ]

    const int tid  = threadIdx.x;
    const int lane = tid & 31;
    const int wid  = tid >> 5;
    const int wm   = wid >> 2;        // 0..1  (M direction)
    const int wn   = wid & 3;         // 0..3  (N direction)
    const int bm   = blockIdx.y * 128;
    const int bn   = blockIdx.x * 128;

    // g2s assignment: A tile 128x16 as 512 float4 (2 per thread),
    //                 B tile 16x128 as 512 float4 (2 per thread)
    const int a_row = tid >> 2;       // 0..63 (rep adds +64)
    const int a_kq  = tid & 3;        // which float4 along k
    const int b_kr  = tid >> 5;       // 0..7  (rep adds +8)
    const int b_nq  = tid & 31;       // which float4 along n

    const float* Ap = A + (size_t)(bm + a_row) * K + 4 * a_kq;
    const float* Bp = B + (size_t)b_kr * N + bn + 4 * b_nq;

    // Precomputed scatter offsets (j-th element adds 4j for A, 8j for B)
    int a_off[2], b_off[2];
    #pragma unroll
    for (int r = 0; r < 2; r++) {
        int row = a_row + 64 * r;
        int s   = a_kq >> 1, mt = row >> 4, mm = row & 15;
        a_off[r] = s * 1024 + mt * 128 + ((mm & 7) << 4) + ((a_kq & 1) << 1) + (mm >> 3);
        int kr = b_kr + 8 * r;
        int ks = kr >> 3, kk = kr & 7;
        b_off[r] = ks * 1024 + 32 * b_nq + ((kk & 3) << 1) + (kk >> 2);
    }

    float acc[4][4][4];
    #pragma unroll
    for (int i = 0; i < 4; i++)
        #pragma unroll
        for (int j = 0; j < 4; j++)
            #pragma unroll
            for (int k = 0; k < 4; k++) acc[i][j][k] = 0.f;

    float4 ar0, ar1, br0, br1;
    const int nstage = K >> 4;

    // prologue: stage 0
    ar0 = *(const float4*)(Ap);
    ar1 = *(const float4*)(Ap + (size_t)64 * K);
    br0 = *(const float4*)(Bp);
    br1 = *(const float4*)(Bp + (size_t)8 * N);
    {
        float va0[4] = {ar0.x, ar0.y, ar0.z, ar0.w};
        float va1[4] = {ar1.x, ar1.y, ar1.z, ar1.w};
        float vb0[4] = {br0.x, br0.y, br0.z, br0.w};
        float vb1[4] = {br1.x, br1.y, br1.z, br1.w};
        #pragma unroll
        for (int j = 0; j < 4; j++) {
            As[0][a_off[0] + 4 * j] = f2tf32(va0[j]);
            As[0][a_off[1] + 4 * j] = f2tf32(va1[j]);
            Bs[0][b_off[0] + 8 * j] = f2tf32(vb0[j]);
            Bs[0][b_off[1] + 8 * j] = f2tf32(vb1[j]);
        }
    }
    __syncthreads();

    for (int st = 0; st < nstage; st++) {
        const int buf = st & 1;
        if (st + 1 < nstage) {
            int k0 = (st + 1) << 4;
            ar0 = *(const float4*)(Ap + k0);
            ar1 = *(const float4*)(Ap + k0 + (size_t)64 * K);
            br0 = *(const float4*)(Bp + (size_t)k0 * N);
            br1 = *(const float4*)(Bp + (size_t)(k0 + 8) * N);
        }

        // compute on current buffer: 2 k8 sub-steps
        #pragma unroll
        for (int s = 0; s < 2; s++) {
            uint4 af[4];
            uint2 bf[4];
            #pragma unroll
            for (int mt = 0; mt < 4; mt++)
                af[mt] = *(const uint4*)&As[buf][s * 1024 + (wm * 4 + mt) * 128 + lane * 4];
            #pragma unroll
            for (int nt = 0; nt < 4; nt++)
                bf[nt] = *(const uint2*)&Bs[buf][s * 1024 + (wn * 4 + nt) * 64 + lane * 2];
            #pragma unroll
            for (int mt = 0; mt < 4; mt++)
                #pragma unroll
                for (int nt = 0; nt < 4; nt++)
                    mma_tf32(acc[mt][nt], af[mt], bf[nt]);
        }

        if (st + 1 < nstage) {
            const int nb = (st + 1) & 1;
            float va0[4] = {ar0.x, ar0.y, ar0.z, ar0.w};
            float va1[4] = {ar1.x, ar1.y, ar1.z, ar1.w};
            float vb0[4] = {br0.x, br0.y, br0.z, br0.w};
            float vb1[4] = {br1.x, br1.y, br1.z, br1.w};
            #pragma unroll
            for (int j = 0; j < 4; j++) {
                As[nb][a_off[0] + 4 * j] = f2tf32(va0[j]);
                As[nb][a_off[1] + 4 * j] = f2tf32(va1[j]);
                Bs[nb][b_off[0] + 8 * j] = f2tf32(vb0[j]);
                Bs[nb][b_off[1] + 8 * j] = f2tf32(vb1[j]);
            }
        }
        __syncthreads();
    }

    // epilogue: c0=(r,c), c1=(r,c+1), c2=(r+8,c), c3=(r+8,c+1)
    #pragma unroll
    for (int mt = 0; mt < 4; mt++) {
        #pragma unroll
        for (int nt = 0; nt < 4; nt++) {
            int row0 = bm + wm * 64 + mt * 16 + (lane >> 2);
            int col  = bn + wn * 32 + nt * 8 + (lane & 3) * 2;
            float bx = bias[col], by = bias[col + 1];
            #pragma unroll
            for (int half = 0; half < 2; half++) {
                int row = row0 + 8 * half;
                float v0 = acc[mt][nt][2 * half + 0] + bx;
                float v1 = acc[mt][nt][2 * half + 1] + by;
                if (RELU) { v0 = fmaxf(v0, 0.f); v1 = fmaxf(v1, 0.f); }
                if (RES) {
                    const float2 rr = *(const float2*)&res[(size_t)row * N + col];
                    v0 += rr.x; v1 += rr.y;
                }
                float2 ov; ov.x = v0; ov.y = v1;
                *(float2*)&C[(size_t)row * N + col] = ov;
            }
        }
    }
}

// ---------------------------------------------------------------------------
// Flash attention (fp32, online softmax). One block = (b,h, 64-query tile).
// ---------------------------------------------------------------------------
__global__ __launch_bounds__(256) void attn_kernel(const int* __restrict__ mask)
{
    __shared__ float Qs [64 * 64];   // Qs[r][d]
    __shared__ float KPs[64 * 64];   // first Kt[d][c], then P[r][c]
    __shared__ float Vs [64 * 64];   // Vs[c][d]

    int tid = threadIdx.x;
    int tx = tid & 15, ty = tid >> 4;
    int b = blockIdx.y >> 4;
    int h = blockIdx.y & 15;
    int qt = blockIdx.x;

    int base_q = (b * SS + qt * 64) * DD + h * 64;
    for (int idx = tid; idx < 4096; idx += 256) {
        int r = idx >> 6, d = idx & 63;
        Qs[idx] = g_q[base_q + r * DD + d];
    }

    float m[4], l[4], o[4][4];
    #pragma unroll
    for (int i = 0; i < 4; i++) {
        m[i] = -1e30f; l[i] = 0.f;
        #pragma unroll
        for (int j = 0; j < 4; j++) o[i][j] = 0.f;
    }

    for (int kt = 0; kt < SS / 64; kt++) {
        __syncthreads();
        int base_k = (b * SS + kt * 64) * DD + h * 64;
        for (int idx = tid; idx < 4096; idx += 256) {
            int c = idx >> 6, d = idx & 63;
            KPs[d * 64 + c] = g_k[base_k + c * DD + d];   // transposed
            Vs[idx]         = g_v[base_k + c * DD + d];
        }
        __syncthreads();

        float s[4][4];
        #pragma unroll
        for (int i = 0; i < 4; i++)
            #pragma unroll
            for (int j = 0; j < 4; j++) s[i][j] = 0.f;
        #pragma unroll 16
        for (int d = 0; d < 64; d++) {
            float qv[4];
            #pragma unroll
            for (int i = 0; i < 4; i++) qv[i] = Qs[(ty * 4 + i) * 64 + d];
            float4 kv = *(const float4*)&KPs[d * 64 + tx * 4];
            float kr[4] = {kv.x, kv.y, kv.z, kv.w};
            #pragma unroll
            for (int i = 0; i < 4; i++)
                #pragma unroll
                for (int j = 0; j < 4; j++)
                    s[i][j] += qv[i] * kr[j];
        }

        int mbase = b * SS + kt * 64 + tx * 4;
        #pragma unroll
        for (int j = 0; j < 4; j++) {
            int mv = mask[mbase + j];
            #pragma unroll
            for (int i = 0; i < 4; i++)
                s[i][j] = mv ? s[i][j] * 0.125f : -1e9f;
        }

        float nm[4], alpha[4], p[4][4], rs[4];
        #pragma unroll
        for (int i = 0; i < 4; i++) {
            float tm = fmaxf(fmaxf(s[i][0], s[i][1]), fmaxf(s[i][2], s[i][3]));
            #pragma unroll
            for (int off = 8; off; off >>= 1)
                tm = fmaxf(tm, __shfl_xor_sync(0xffffffffu, tm, off, 16));
            nm[i] = fmaxf(m[i], tm);
            alpha[i] = __expf(m[i] - nm[i]);
            m[i] = nm[i];
        }
        #pragma unroll
        for (int i = 0; i < 4; i++) {
            float rsum = 0.f;
            #pragma unroll
            for (int j = 0; j < 4; j++) {
                p[i][j] = __expf(s[i][j] - nm[i]);
                rsum += p[i][j];
            }
            #pragma unroll
            for (int off = 8; off; off >>= 1)
                rsum += __shfl_xor_sync(0xffffffffu, rsum, off, 16);
            rs[i] = rsum;
        }
        #pragma unroll
        for (int i = 0; i < 4; i++) {
            l[i] = l[i] * alpha[i] + rs[i];
            #pragma unroll
            for (int j = 0; j < 4; j++) o[i][j] *= alpha[i];
        }

        __syncthreads();
        #pragma unroll
        for (int i = 0; i < 4; i++)
            *(float4*)&KPs[(ty * 4 + i) * 64 + tx * 4] =
                make_float4(p[i][0], p[i][1], p[i][2], p[i][3]);
        __syncthreads();

        #pragma unroll 16
        for (int c = 0; c < 64; c++) {
            float pv[4];
            #pragma unroll
            for (int i = 0; i < 4; i++) pv[i] = KPs[(ty * 4 + i) * 64 + c];
            float4 vv = *(const float4*)&Vs[c * 64 + tx * 4];
            float vr[4] = {vv.x, vv.y, vv.z, vv.w};
            #pragma unroll
            for (int i = 0; i < 4; i++)
                #pragma unroll
                for (int j = 0; j < 4; j++)
                    o[i][j] += pv[i] * vr[j];
        }
    }

    int base_o = (b * SS + qt * 64) * DD + h * 64;
    #pragma unroll
    for (int i = 0; i < 4; i++) {
        float inv = 1.0f / l[i];
        #pragma unroll
        for (int j = 0; j < 4; j++)
            g_o[base_o + (ty * 4 + i) * DD + tx * 4 + j] = o[i][j] * inv;
    }
}

// ---------------------------------------------------------------------------
// Launch
// ---------------------------------------------------------------------------
extern "C" void kernel_launch(void* const* d_in, const int* in_sizes, int n_in,
                              void* d_out, int out_size)
{
    (void)in_sizes; (void)n_in; (void)out_size;
    const int*   tokens = (const int*)  d_in[0];
    const int*   mask   = (const int*)  d_in[1];
    const float* emb    = (const float*)d_in[2];
    const float* pe     = (const float*)d_in[3];
    const float* Wq     = (const float*)d_in[4];
    const float* bq     = (const float*)d_in[5];
    const float* Wk     = (const float*)d_in[6];
    const float* bk     = (const float*)d_in[7];
    const float* Wv     = (const float*)d_in[8];
    const float* bv     = (const float*)d_in[9];
    const float* Wo     = (const float*)d_in[10];
    const float* bo     = (const float*)d_in[11];
    const float* w1     = (const float*)d_in[12];
    const float* b1     = (const float*)d_in[13];
    const float* w2     = (const float*)d_in[14];
    const float* b2     = (const float*)d_in[15];
    const float* ln_a   = (const float*)d_in[16];
    const float* ln_b   = (const float*)d_in[17];
    const float* fa     = (const float*)d_in[18];
    const float* fb     = (const float*)d_in[19];
    float* out = (float*)d_out;

    float *px, *ph, *pq, *pk, *pv, *po, *pmid;
    cudaGetSymbolAddress((void**)&px,   g_x);
    cudaGetSymbolAddress((void**)&ph,   g_h);
    cudaGetSymbolAddress((void**)&pq,   g_q);
    cudaGetSymbolAddress((void**)&pk,   g_k);
    cudaGetSymbolAddress((void**)&pv,   g_v);
    cudaGetSymbolAddress((void**)&po,   g_o);
    cudaGetSymbolAddress((void**)&pmid, g_mid);

    embed_kernel<<<(MM * DD) / 256, 256>>>(tokens, emb, pe);

    dim3 gD(DD / 128, MM / 128);   // N=1024 output GEMMs
    dim3 gF(FF / 128, MM / 128);   // N=4096 output GEMMs

    for (int l = 0; l < LL; l++) {
        const float* lnA = ln_a + l * 2 * DD;
        const float* lnB = ln_b + l * 2 * DD;

        // --- attention sublayer ---
        ln_kernel<<<MM, 256>>>(px, ph, lnA, lnB);
        tgemm_kernel<false, false><<<gD, 256>>>(ph, Wq + l * DD * DD, bq + l * DD,
                                                nullptr, pq, MM, DD, DD);
        tgemm_kernel<false, false><<<gD, 256>>>(ph, Wk + l * DD * DD, bk + l * DD,
                                                nullptr, pk, MM, DD, DD);
        tgemm_kernel<false, false><<<gD, 256>>>(ph, Wv + l * DD * DD, bv + l * DD,
                                                nullptr, pv, MM, DD, DD);
        attn_kernel<<<dim3(SS / 64, BB * HH), 256>>>(mask);
        tgemm_kernel<false, true><<<gD, 256>>>(po, Wo + l * DD * DD, bo + l * DD,
                                               px, px, MM, DD, DD);

        // --- FFN sublayer ---
        ln_kernel<<<MM, 256>>>(px, ph, lnA + DD, lnB + DD);
        tgemm_kernel<true, false><<<gF, 256>>>(ph, w1 + l * DD * FF, b1 + l * FF,
                                               nullptr, pmid, MM, FF, DD);
        tgemm_kernel<false, true><<<gD, 256>>>(pmid, w2 + l * FF * DD, b2 + l * DD,
                                               px, px, MM, DD, FF);
    }

    ln_kernel<<<MM, 256>>>(px, out, fa, fb);
}

// round 5
// speedup vs baseline: 3.4342x; 3.4342x over previous
#include <cuda_runtime.h>
#include <cuda_bf16.h>
#include <math.h>

// ---------------------------------------------------------------------------
// Problem constants
// ---------------------------------------------------------------------------
#define BB 2
#define SS 2048
#define DD 1024
#define HH 16
#define FF 4096
#define LL 3
#define MM (BB*SS)          // 4096 rows

// ---------------------------------------------------------------------------
// Scratch (device globals)
// ---------------------------------------------------------------------------
__device__ float g_x  [MM*DD];
__device__ float g_h  [MM*DD];
__device__ float g_q  [MM*DD];
__device__ float g_k  [MM*DD];
__device__ float g_v  [MM*DD];
__device__ float g_o  [MM*DD];
__device__ float g_mid[MM*FF];

// ---------------------------------------------------------------------------
// Small helpers
// ---------------------------------------------------------------------------
__device__ __forceinline__ unsigned sptr(const void* p) {
    return (unsigned)__cvta_generic_to_shared(p);
}
// pack {lo, hi} floats -> bf16x2 (lo in low half)
__device__ __forceinline__ unsigned pk(float lo, float hi) {
    unsigned d;
    asm("cvt.rn.bf16x2.f32 %0, %1, %2;" : "=r"(d) : "f"(hi), "f"(lo));
    return d;
}
__device__ __forceinline__ void ldsm4(unsigned& r0, unsigned& r1, unsigned& r2,
                                      unsigned& r3, unsigned a) {
    asm volatile("ldmatrix.sync.aligned.m8n8.x4.shared.b16 {%0,%1,%2,%3}, [%4];"
                 : "=r"(r0), "=r"(r1), "=r"(r2), "=r"(r3) : "r"(a));
}
__device__ __forceinline__ void ldsm4t(unsigned& r0, unsigned& r1, unsigned& r2,
                                       unsigned& r3, unsigned a) {
    asm volatile("ldmatrix.sync.aligned.m8n8.x4.trans.shared.b16 {%0,%1,%2,%3}, [%4];"
                 : "=r"(r0), "=r"(r1), "=r"(r2), "=r"(r3) : "r"(a));
}
__device__ __forceinline__ void mma_bf16(float* c, unsigned a0, unsigned a1,
                                         unsigned a2, unsigned a3,
                                         unsigned b0, unsigned b1) {
    asm volatile(
        "mma.sync.aligned.m16n8k16.row.col.f32.bf16.bf16.f32 "
        "{%0,%1,%2,%3},{%4,%5,%6,%7},{%8,%9},{%0,%1,%2,%3};"
        : "+f"(c[0]), "+f"(c[1]), "+f"(c[2]), "+f"(c[3])
        : "r"(a0), "r"(a1), "r"(a2), "r"(a3), "r"(b0), "r"(b1));
}

// ---------------------------------------------------------------------------
// Embedding + positional encoding
// ---------------------------------------------------------------------------
__global__ __launch_bounds__(256) void embed_kernel(
    const int* __restrict__ tokens, const float* __restrict__ emb,
    const float* __restrict__ pe)
{
    int idx = blockIdx.x * 256 + threadIdx.x;
    int bs  = idx >> 10;
    int d   = idx & 1023;
    int tok = tokens[bs];
    int s   = bs & (SS - 1);
    g_x[idx] = emb[tok * DD + d] * 32.0f + pe[s * DD + d];
}

// ---------------------------------------------------------------------------
// LayerNorm (torch: Bessel std, eps on std)
// ---------------------------------------------------------------------------
__global__ __launch_bounds__(256) void ln_kernel(
    const float* __restrict__ src, float* __restrict__ dst,
    const float* __restrict__ ga, const float* __restrict__ gb)
{
    __shared__ float red[8];
    __shared__ float bval;
    int row = blockIdx.x, tid = threadIdx.x;
    float4 v = ((const float4*)(src + row * DD))[tid];

    float s = v.x + v.y + v.z + v.w;
    #pragma unroll
    for (int off = 16; off; off >>= 1) s += __shfl_xor_sync(0xffffffffu, s, off);
    if ((tid & 31) == 0) red[tid >> 5] = s;
    __syncthreads();
    if (tid == 0) {
        float t = 0.f;
        #pragma unroll
        for (int i = 0; i < 8; i++) t += red[i];
        bval = t * (1.0f / DD);
    }
    __syncthreads();
    float mean = bval;

    float dx = v.x - mean, dy = v.y - mean, dz = v.z - mean, dw = v.w - mean;
    float sq = dx*dx + dy*dy + dz*dz + dw*dw;
    #pragma unroll
    for (int off = 16; off; off >>= 1) sq += __shfl_xor_sync(0xffffffffu, sq, off);
    if ((tid & 31) == 0) red[tid >> 5] = sq;
    __syncthreads();
    if (tid == 0) {
        float t = 0.f;
        #pragma unroll
        for (int i = 0; i < 8; i++) t += red[i];
        bval = t;
    }
    __syncthreads();
    float stdv = sqrtf(bval * (1.0f / (DD - 1)));
    float inv  = 1.0f / (stdv + 1e-6f);

    int c = tid * 4;
    float4 o;
    o.x = ga[c + 0] * dx * inv + gb[c + 0];
    o.y = ga[c + 1] * dy * inv + gb[c + 1];
    o.z = ga[c + 2] * dz * inv + gb[c + 2];
    o.w = ga[c + 3] * dw * inv + gb[c + 3];
    ((float4*)(dst + row * DD))[tid] = o;
}

// ---------------------------------------------------------------------------
// bf16 tensor-core GEMM: C = A @ B + bias (+relu) (+residual)
// 128x128x32 tile, 256 thr = 8 warps (2m x 4n), warp tile 64x32.
// As: [128 rows][32 bf16] (64B rows), chunk swizzle c ^ ((r>>1)&3)
// Bs: [32 rows][128 bf16] (256B rows), chunk swizzle c ^ (r&7), ldmatrix.trans
// ---------------------------------------------------------------------------
template<bool RELU, bool RES>
__global__ __launch_bounds__(256) void bgemm_kernel(
    const float* __restrict__ A, const float* __restrict__ B,
    const float* __restrict__ bias, const float* __restrict__ res,
    float* __restrict__ C, int M, int N, int K)
{
    __shared__ __align__(16) unsigned As[2][2048];   // 128*16 uints = 8KB
    __shared__ __align__(16) unsigned Bs[2][2048];   // 32*64 uints  = 8KB

    const int tid = threadIdx.x, lane = tid & 31, wid = tid >> 5;
    const int wm = wid >> 2, wn = wid & 3;
    const int bm = blockIdx.y * 128, bn = blockIdx.x * 128;

    // g2s: A: thread -> row tid>>1, k-half (tid&1)*16 (4 float4)
    //      B: thread -> k-row tid>>3, n-base (tid&7)*16 (4 float4)
    const int ar = tid >> 1, ak = (tid & 1) * 16;
    const int bk = tid >> 3, bn0 = (tid & 7) * 16;
    const float* Ap = A + (size_t)(bm + ar) * K + ak;
    const float* Bp = B + (size_t)bk * N + bn + bn0;

    int a_soff[4], b_soff[4];
    #pragma unroll
    for (int j = 0; j < 4; j++) {
        int ca = (tid & 1) * 2 + (j >> 1);
        a_soff[j] = ar * 16 + ((ca ^ ((ar >> 1) & 3)) << 2) + (j & 1) * 2;
        int cb = (tid & 7) * 2 + (j >> 1);
        b_soff[j] = bk * 64 + ((cb ^ (bk & 7)) << 2) + (j & 1) * 2;
    }

    // ldmatrix lane geometry
    const int ra0 = wm * 64 + (lane & 7) + ((lane >> 3) & 1) * 8;
    const int sA  = (ra0 >> 1) & 3;
    const int rb0 = (lane & 7) + ((lane >> 3) & 1) * 8;
    const int sB  = lane & 7;
    const int top = lane >> 4;

    float acc[4][4][4];
    #pragma unroll
    for (int i = 0; i < 4; i++)
        #pragma unroll
        for (int j = 0; j < 4; j++)
            #pragma unroll
            for (int k = 0; k < 4; k++) acc[i][j][k] = 0.f;

    uint2 sa[4], sb[4];
    const int nst = K >> 5;

    // prologue: stage 0
    #pragma unroll
    for (int j = 0; j < 4; j++) {
        float4 v = *(const float4*)(Ap + 4 * j);
        sa[j] = make_uint2(pk(v.x, v.y), pk(v.z, v.w));
        float4 w = *(const float4*)(Bp + 4 * j);
        sb[j] = make_uint2(pk(w.x, w.y), pk(w.z, w.w));
    }
    #pragma unroll
    for (int j = 0; j < 4; j++) {
        *(uint2*)&As[0][a_soff[j]] = sa[j];
        *(uint2*)&Bs[0][b_soff[j]] = sb[j];
    }
    __syncthreads();

    for (int st = 0; st < nst; st++) {
        const int buf = st & 1;
        if (st + 1 < nst) {
            int k0 = (st + 1) << 5;
            #pragma unroll
            for (int j = 0; j < 4; j++) {
                float4 v = *(const float4*)(Ap + k0 + 4 * j);
                sa[j] = make_uint2(pk(v.x, v.y), pk(v.z, v.w));
                float4 w = *(const float4*)(Bp + (size_t)k0 * N + 4 * j);
                sb[j] = make_uint2(pk(w.x, w.y), pk(w.z, w.w));
            }
        }

        const unsigned abase = sptr(&As[buf][0]);
        const unsigned bbase = sptr(&Bs[buf][0]);
        #pragma unroll
        for (int s = 0; s < 2; s++) {
            unsigned af[4][4];
            #pragma unroll
            for (int mt = 0; mt < 4; mt++) {
                int row = ra0 + mt * 16;
                int c   = 2 * s + top;
                ldsm4(af[mt][0], af[mt][1], af[mt][2], af[mt][3],
                      abase + (row << 6) + ((c ^ sA) << 4));
            }
            unsigned bf[4][2];
            #pragma unroll
            for (int g = 0; g < 2; g++) {
                int row = s * 16 + rb0;
                int c   = wn * 4 + 2 * g + top;
                unsigned r0, r1, r2, r3;
                ldsm4t(r0, r1, r2, r3, bbase + (row << 8) + ((c ^ sB) << 4));
                bf[2*g][0] = r0; bf[2*g][1] = r1;
                bf[2*g+1][0] = r2; bf[2*g+1][1] = r3;
            }
            #pragma unroll
            for (int mt = 0; mt < 4; mt++)
                #pragma unroll
                for (int nt = 0; nt < 4; nt++)
                    mma_bf16(acc[mt][nt], af[mt][0], af[mt][1], af[mt][2],
                             af[mt][3], bf[nt][0], bf[nt][1]);
        }

        if (st + 1 < nst) {
            const int nb = (st + 1) & 1;
            #pragma unroll
            for (int j = 0; j < 4; j++) {
                *(uint2*)&As[nb][a_soff[j]] = sa[j];
                *(uint2*)&Bs[nb][b_soff[j]] = sb[j];
            }
        }
        __syncthreads();
    }

    // epilogue
    #pragma unroll
    for (int mt = 0; mt < 4; mt++) {
        #pragma unroll
        for (int nt = 0; nt < 4; nt++) {
            int row0 = bm + wm * 64 + mt * 16 + (lane >> 2);
            int col  = bn + wn * 32 + nt * 8 + (lane & 3) * 2;
            float bx = bias[col], by = bias[col + 1];
            #pragma unroll
            for (int half = 0; half < 2; half++) {
                int row = row0 + 8 * half;
                float v0 = acc[mt][nt][2 * half + 0] + bx;
                float v1 = acc[mt][nt][2 * half + 1] + by;
                if (RELU) { v0 = fmaxf(v0, 0.f); v1 = fmaxf(v1, 0.f); }
                if (RES) {
                    const float2 rr = *(const float2*)&res[(size_t)row * N + col];
                    v0 += rr.x; v1 += rr.y;
                }
                float2 ov; ov.x = v0; ov.y = v1;
                *(float2*)&C[(size_t)row * N + col] = ov;
            }
        }
    }
}

// ---------------------------------------------------------------------------
// Flash attention, bf16 tensor cores. Block = (b,h,64-query tile), 128 thr.
// Q/K/V tiles 64x64 bf16 in smem (128B rows, chunk swizzle c ^ (r&7)).
// S = Q K^T via mma (K frag: non-trans ldmatrix); softmax on C fragments;
// P repacked to A fragments in registers; O += P V (V frag: ldmatrix.trans).
// ---------------------------------------------------------------------------
__global__ __launch_bounds__(128) void attn_kernel(const int* __restrict__ mask)
{
    __shared__ __align__(16) unsigned Qs[64 * 32];   // 8KB
    __shared__ __align__(16) unsigned Ks[64 * 32];   // 8KB
    __shared__ __align__(16) unsigned Vs[64 * 32];   // 8KB
    __shared__ float mb[64];

    const int tid = threadIdx.x, lane = tid & 31, w = tid >> 5;
    const int b = blockIdx.y >> 4, h = blockIdx.y & 15, qt = blockIdx.x;

    // g2s: row tid>>1, d-half (tid&1)*32, 8 float4
    const int gr = tid >> 1, gd = (tid & 1) * 32;
    int soff[8];
    #pragma unroll
    for (int j = 0; j < 8; j++) {
        int c = (tid & 1) * 4 + (j >> 1);
        soff[j] = gr * 32 + ((c ^ (gr & 7)) << 2) + (j & 1) * 2;
    }

    const float* Qg = g_q + (size_t)(b * SS + qt * 64 + gr) * DD + h * 64 + gd;
    #pragma unroll
    for (int j = 0; j < 8; j++) {
        float4 v = *(const float4*)(Qg + 4 * j);
        *(uint2*)&Qs[soff[j]] = make_uint2(pk(v.x, v.y), pk(v.z, v.w));
    }
    __syncthreads();

    // hoist Q fragments (invariant across key tiles)
    const int rq0 = w * 16 + (lane & 7) + ((lane >> 3) & 1) * 8;
    const int rk0 = (lane & 7) + ((lane >> 3) & 1) * 8;
    const int top = lane >> 4;
    const unsigned qb = sptr(Qs), kb = sptr(Ks), vb = sptr(Vs);
    unsigned qf[4][4];
    #pragma unroll
    for (int s = 0; s < 4; s++) {
        int c = 2 * s + top;
        ldsm4(qf[s][0], qf[s][1], qf[s][2], qf[s][3],
              qb + (rq0 << 7) + ((c ^ (rq0 & 7)) << 4));
    }

    float m0 = -1e30f, m1 = -1e30f, l0 = 0.f, l1 = 0.f;
    float oacc[8][4];
    #pragma unroll
    for (int j = 0; j < 8; j++)
        #pragma unroll
        for (int k = 0; k < 4; k++) oacc[j][k] = 0.f;

    const float* Kg = g_k + (size_t)(b * SS) * DD + h * 64;
    const float* Vg = g_v + (size_t)(b * SS) * DD + h * 64;

    for (int kt = 0; kt < SS / 64; kt++) {
        __syncthreads();   // prev iter done with Ks/Vs
        const float* Kt = Kg + (size_t)(kt * 64 + gr) * DD + gd;
        const float* Vt = Vg + (size_t)(kt * 64 + gr) * DD + gd;
        #pragma unroll
        for (int j = 0; j < 8; j++) {
            float4 v = *(const float4*)(Kt + 4 * j);
            *(uint2*)&Ks[soff[j]] = make_uint2(pk(v.x, v.y), pk(v.z, v.w));
            float4 u = *(const float4*)(Vt + 4 * j);
            *(uint2*)&Vs[soff[j]] = make_uint2(pk(u.x, u.y), pk(u.z, u.w));
        }
        if (tid < 64) mb[tid] = mask[b * SS + kt * 64 + tid] ? 0.f : -1e9f;
        __syncthreads();

        // ---- S = Q K^T ----
        float sacc[8][4];
        #pragma unroll
        for (int j = 0; j < 8; j++)
            #pragma unroll
            for (int k = 0; k < 4; k++) sacc[j][k] = 0.f;

        #pragma unroll
        for (int s = 0; s < 4; s++) {
            unsigned bf[8][2];
            #pragma unroll
            for (int g = 0; g < 4; g++) {
                int row = g * 16 + rk0;           // key row
                int c   = 2 * s + top;            // d chunk
                unsigned r0, r1, r2, r3;
                ldsm4(r0, r1, r2, r3, kb + (row << 7) + ((c ^ (lane & 7)) << 4));
                bf[2*g][0] = r0; bf[2*g][1] = r2;     // non-trans pairing
                bf[2*g+1][0] = r1; bf[2*g+1][1] = r3;
            }
            #pragma unroll
            for (int j = 0; j < 8; j++)
                mma_bf16(sacc[j], qf[s][0], qf[s][1], qf[s][2], qf[s][3],
                         bf[j][0], bf[j][1]);
        }

        // ---- scale + mask + online softmax on fragments ----
        float mx0 = -1e30f, mx1 = -1e30f;
        #pragma unroll
        for (int j = 0; j < 8; j++) {
            float2 mj = *(const float2*)&mb[j * 8 + (lane & 3) * 2];
            sacc[j][0] = sacc[j][0] * 0.125f + mj.x;
            sacc[j][1] = sacc[j][1] * 0.125f + mj.y;
            sacc[j][2] = sacc[j][2] * 0.125f + mj.x;
            sacc[j][3] = sacc[j][3] * 0.125f + mj.y;
            mx0 = fmaxf(mx0, fmaxf(sacc[j][0], sacc[j][1]));
            mx1 = fmaxf(mx1, fmaxf(sacc[j][2], sacc[j][3]));
        }
        mx0 = fmaxf(mx0, __shfl_xor_sync(0xffffffffu, mx0, 1, 4));
        mx0 = fmaxf(mx0, __shfl_xor_sync(0xffffffffu, mx0, 2, 4));
        mx1 = fmaxf(mx1, __shfl_xor_sync(0xffffffffu, mx1, 1, 4));
        mx1 = fmaxf(mx1, __shfl_xor_sync(0xffffffffu, mx1, 2, 4));

        float nm0 = fmaxf(m0, mx0), nm1 = fmaxf(m1, mx1);
        float al0 = __expf(m0 - nm0), al1 = __expf(m1 - nm1);
        m0 = nm0; m1 = nm1;

        float rs0 = 0.f, rs1 = 0.f;
        #pragma unroll
        for (int j = 0; j < 8; j++) {
            sacc[j][0] = __expf(sacc[j][0] - nm0);
            sacc[j][1] = __expf(sacc[j][1] - nm0);
            sacc[j][2] = __expf(sacc[j][2] - nm1);
            sacc[j][3] = __expf(sacc[j][3] - nm1);
            rs0 += sacc[j][0] + sacc[j][1];
            rs1 += sacc[j][2] + sacc[j][3];
        }
        rs0 += __shfl_xor_sync(0xffffffffu, rs0, 1, 4);
        rs0 += __shfl_xor_sync(0xffffffffu, rs0, 2, 4);
        rs1 += __shfl_xor_sync(0xffffffffu, rs1, 1, 4);
        rs1 += __shfl_xor_sync(0xffffffffu, rs1, 2, 4);
        l0 = l0 * al0 + rs0;
        l1 = l1 * al1 + rs1;

        #pragma unroll
        for (int j = 0; j < 8; j++) {
            oacc[j][0] *= al0; oacc[j][1] *= al0;
            oacc[j][2] *= al1; oacc[j][3] *= al1;
        }

        // ---- O += P V ----
        #pragma unroll
        for (int k4 = 0; k4 < 4; k4++) {
            unsigned pa0 = pk(sacc[2*k4][0],   sacc[2*k4][1]);
            unsigned pa1 = pk(sacc[2*k4][2],   sacc[2*k4][3]);
            unsigned pa2 = pk(sacc[2*k4+1][0], sacc[2*k4+1][1]);
            unsigned pa3 = pk(sacc[2*k4+1][2], sacc[2*k4+1][3]);
            #pragma unroll
            for (int g = 0; g < 4; g++) {
                int row = k4 * 16 + rk0;          // key row
                int c   = 2 * g + top;            // d chunk
                unsigned r0, r1, r2, r3;
                ldsm4t(r0, r1, r2, r3, vb + (row << 7) + ((c ^ (lane & 7)) << 4));
                mma_bf16(oacc[2*g],   pa0, pa1, pa2, pa3, r0, r1);
                mma_bf16(oacc[2*g+1], pa0, pa1, pa2, pa3, r2, r3);
            }
        }
    }

    // ---- write O / l ----
    float i0 = 1.0f / l0, i1 = 1.0f / l1;
    int row0 = b * SS + qt * 64 + w * 16 + (lane >> 2);
    float* O0 = g_o + (size_t)row0 * DD + h * 64;
    float* O1 = O0 + (size_t)8 * DD;
    #pragma unroll
    for (int j = 0; j < 8; j++) {
        int d = j * 8 + (lane & 3) * 2;
        *(float2*)&O0[d] = make_float2(oacc[j][0] * i0, oacc[j][1] * i0);
        *(float2*)&O1[d] = make_float2(oacc[j][2] * i1, oacc[j][3] * i1);
    }
}

// ---------------------------------------------------------------------------
// Launch
// ---------------------------------------------------------------------------
extern "C" void kernel_launch(void* const* d_in, const int* in_sizes, int n_in,
                              void* d_out, int out_size)
{
    (void)in_sizes; (void)n_in; (void)out_size;
    const int*   tokens = (const int*)  d_in[0];
    const int*   mask   = (const int*)  d_in[1];
    const float* emb    = (const float*)d_in[2];
    const float* pe     = (const float*)d_in[3];
    const float* Wq     = (const float*)d_in[4];
    const float* bq     = (const float*)d_in[5];
    const float* Wk     = (const float*)d_in[6];
    const float* bk     = (const float*)d_in[7];
    const float* Wv     = (const float*)d_in[8];
    const float* bv     = (const float*)d_in[9];
    const float* Wo     = (const float*)d_in[10];
    const float* bo     = (const float*)d_in[11];
    const float* w1     = (const float*)d_in[12];
    const float* b1     = (const float*)d_in[13];
    const float* w2     = (const float*)d_in[14];
    const float* b2     = (const float*)d_in[15];
    const float* ln_a   = (const float*)d_in[16];
    const float* ln_b   = (const float*)d_in[17];
    const float* fa     = (const float*)d_in[18];
    const float* fb     = (const float*)d_in[19];
    float* out = (float*)d_out;

    float *px, *ph, *pq, *pk_, *pv, *po, *pmid;
    cudaGetSymbolAddress((void**)&px,   g_x);
    cudaGetSymbolAddress((void**)&ph,   g_h);
    cudaGetSymbolAddress((void**)&pq,   g_q);
    cudaGetSymbolAddress((void**)&pk_,  g_k);
    cudaGetSymbolAddress((void**)&pv,   g_v);
    cudaGetSymbolAddress((void**)&po,   g_o);
    cudaGetSymbolAddress((void**)&pmid, g_mid);

    embed_kernel<<<(MM * DD) / 256, 256>>>(tokens, emb, pe);

    dim3 gD(DD / 128, MM / 128);
    dim3 gF(FF / 128, MM / 128);

    for (int l = 0; l < LL; l++) {
        const float* lnA = ln_a + l * 2 * DD;
        const float* lnB = ln_b + l * 2 * DD;

        ln_kernel<<<MM, 256>>>(px, ph, lnA, lnB);
        bgemm_kernel<false, false><<<gD, 256>>>(ph, Wq + l * DD * DD, bq + l * DD,
                                                nullptr, pq, MM, DD, DD);
        bgemm_kernel<false, false><<<gD, 256>>>(ph, Wk + l * DD * DD, bk + l * DD,
                                                nullptr, pk_, MM, DD, DD);
        bgemm_kernel<false, false><<<gD, 256>>>(ph, Wv + l * DD * DD, bv + l * DD,
                                                nullptr, pv, MM, DD, DD);
        attn_kernel<<<dim3(SS / 64, BB * HH), 128>>>(mask);
        bgemm_kernel<false, true><<<gD, 256>>>(po, Wo + l * DD * DD, bo + l * DD,
                                               px, px, MM, DD, DD);

        ln_kernel<<<MM, 256>>>(px, ph, lnA + DD, lnB + DD);
        bgemm_kernel<true, false><<<gF, 256>>>(ph, w1 + l * DD * FF, b1 + l * FF,
                                               nullptr, pmid, MM, FF, DD);
        bgemm_kernel<false, true><<<gD, 256>>>(pmid, w2 + l * FF * DD, b2 + l * DD,
                                               px, px, MM, DD, FF);
    }

    ln_kernel<<<MM, 256>>>(px, out, fa, fb);
}

// round 6
// speedup vs baseline: 6.8677x; 1.9998x over previous
#include <cuda_runtime.h>
#include <cuda_bf16.h>
#include <math.h>

// ---------------------------------------------------------------------------
// Problem constants
// ---------------------------------------------------------------------------
#define BB 2
#define SS 2048
#define DD 1024
#define HH 16
#define FF 4096
#define LL 3
#define MM (BB*SS)          // 4096 rows

// ---------------------------------------------------------------------------
// Scratch (device globals)
// ---------------------------------------------------------------------------
__device__ float         g_x  [MM*DD];       // residual stream (fp32 anchor)
__device__ __nv_bfloat16 g_h  [MM*DD];       // LN output
__device__ __nv_bfloat16 g_q  [MM*DD];
__device__ __nv_bfloat16 g_k  [MM*DD];
__device__ __nv_bfloat16 g_v  [MM*DD];
__device__ __nv_bfloat16 g_o  [MM*DD];
__device__ __nv_bfloat16 g_mid[MM*FF];
// bf16 weight caches (converted once per launch)
__device__ __nv_bfloat16 g_wq[LL*DD*DD];
__device__ __nv_bfloat16 g_wk[LL*DD*DD];
__device__ __nv_bfloat16 g_wv[LL*DD*DD];
__device__ __nv_bfloat16 g_wo[LL*DD*DD];
__device__ __nv_bfloat16 g_w1[LL*DD*FF];
__device__ __nv_bfloat16 g_w2[LL*FF*DD];

// ---------------------------------------------------------------------------
// Helpers
// ---------------------------------------------------------------------------
__device__ __forceinline__ unsigned sptr(const void* p) {
    return (unsigned)__cvta_generic_to_shared(p);
}
__device__ __forceinline__ unsigned pk(float lo, float hi) {
    unsigned d;
    asm("cvt.rn.bf16x2.f32 %0, %1, %2;" : "=r"(d) : "f"(hi), "f"(lo));
    return d;
}
__device__ __forceinline__ void cpa16(unsigned dst, const void* src) {
    asm volatile("cp.async.cg.shared.global [%0], [%1], 16;" :: "r"(dst), "l"(src));
}
__device__ __forceinline__ void cp_commit() {
    asm volatile("cp.async.commit_group;");
}
template<int N> __device__ __forceinline__ void cp_wait() {
    asm volatile("cp.async.wait_group %0;" :: "n"(N));
}
__device__ __forceinline__ void ldsm4(unsigned& r0, unsigned& r1, unsigned& r2,
                                      unsigned& r3, unsigned a) {
    asm volatile("ldmatrix.sync.aligned.m8n8.x4.shared.b16 {%0,%1,%2,%3}, [%4];"
                 : "=r"(r0), "=r"(r1), "=r"(r2), "=r"(r3) : "r"(a));
}
__device__ __forceinline__ void ldsm4t(unsigned& r0, unsigned& r1, unsigned& r2,
                                       unsigned& r3, unsigned a) {
    asm volatile("ldmatrix.sync.aligned.m8n8.x4.trans.shared.b16 {%0,%1,%2,%3}, [%4];"
                 : "=r"(r0), "=r"(r1), "=r"(r2), "=r"(r3) : "r"(a));
}
__device__ __forceinline__ void mma_bf16(float* c, unsigned a0, unsigned a1,
                                         unsigned a2, unsigned a3,
                                         unsigned b0, unsigned b1) {
    asm volatile(
        "mma.sync.aligned.m16n8k16.row.col.f32.bf16.bf16.f32 "
        "{%0,%1,%2,%3},{%4,%5,%6,%7},{%8,%9},{%0,%1,%2,%3};"
        : "+f"(c[0]), "+f"(c[1]), "+f"(c[2]), "+f"(c[3])
        : "r"(a0), "r"(a1), "r"(a2), "r"(a3), "r"(b0), "r"(b1));
}

// ---------------------------------------------------------------------------
// fp32 -> bf16 bulk convert (weights). n % 2048 == 0.
// ---------------------------------------------------------------------------
__global__ __launch_bounds__(256) void cvt_kernel(
    const float* __restrict__ src, __nv_bfloat16* __restrict__ dst)
{
    int i = (blockIdx.x * 256 + threadIdx.x) * 8;
    float4 a = *(const float4*)(src + i);
    float4 b = *(const float4*)(src + i + 4);
    uint4 o;
    o.x = pk(a.x, a.y); o.y = pk(a.z, a.w);
    o.z = pk(b.x, b.y); o.w = pk(b.z, b.w);
    *(uint4*)(dst + i) = o;
}

// ---------------------------------------------------------------------------
// Embedding + positional encoding (fp32 residual)
// ---------------------------------------------------------------------------
__global__ __launch_bounds__(256) void embed_kernel(
    const int* __restrict__ tokens, const float* __restrict__ emb,
    const float* __restrict__ pe)
{
    int idx = blockIdx.x * 256 + threadIdx.x;
    int bs  = idx >> 10;
    int d   = idx & 1023;
    int tok = tokens[bs];
    int s   = bs & (SS - 1);
    g_x[idx] = emb[tok * DD + d] * 32.0f + pe[s * DD + d];
}

// ---------------------------------------------------------------------------
// LayerNorm (torch: Bessel std, eps on std). BF16OUT selects output dtype.
// ---------------------------------------------------------------------------
template<bool BF16OUT>
__global__ __launch_bounds__(256) void ln_kernel(
    const float* __restrict__ src, void* __restrict__ dstv,
    const float* __restrict__ ga, const float* __restrict__ gb)
{
    __shared__ float red[8];
    __shared__ float bval;
    int row = blockIdx.x, tid = threadIdx.x;
    float4 v = ((const float4*)(src + row * DD))[tid];

    float s = v.x + v.y + v.z + v.w;
    #pragma unroll
    for (int off = 16; off; off >>= 1) s += __shfl_xor_sync(0xffffffffu, s, off);
    if ((tid & 31) == 0) red[tid >> 5] = s;
    __syncthreads();
    if (tid == 0) {
        float t = 0.f;
        #pragma unroll
        for (int i = 0; i < 8; i++) t += red[i];
        bval = t * (1.0f / DD);
    }
    __syncthreads();
    float mean = bval;

    float dx = v.x - mean, dy = v.y - mean, dz = v.z - mean, dw = v.w - mean;
    float sq = dx*dx + dy*dy + dz*dz + dw*dw;
    #pragma unroll
    for (int off = 16; off; off >>= 1) sq += __shfl_xor_sync(0xffffffffu, sq, off);
    if ((tid & 31) == 0) red[tid >> 5] = sq;
    __syncthreads();
    if (tid == 0) {
        float t = 0.f;
        #pragma unroll
        for (int i = 0; i < 8; i++) t += red[i];
        bval = t;
    }
    __syncthreads();
    float stdv = sqrtf(bval * (1.0f / (DD - 1)));
    float inv  = 1.0f / (stdv + 1e-6f);

    int c = tid * 4;
    float o0 = ga[c + 0] * dx * inv + gb[c + 0];
    float o1 = ga[c + 1] * dy * inv + gb[c + 1];
    float o2 = ga[c + 2] * dz * inv + gb[c + 2];
    float o3 = ga[c + 3] * dw * inv + gb[c + 3];
    if (BF16OUT) {
        __nv_bfloat16* dst = (__nv_bfloat16*)dstv;
        uint2 ov; ov.x = pk(o0, o1); ov.y = pk(o2, o3);
        *(uint2*)&dst[row * DD + c] = ov;
    } else {
        float* dst = (float*)dstv;
        float4 ov; ov.x = o0; ov.y = o1; ov.z = o2; ov.w = o3;
        *(float4*)&dst[row * DD + c] = ov;
    }
}

// ---------------------------------------------------------------------------
// bf16 tensor-core GEMM with 3-stage cp.async pipeline.
// C = A @ B + bias (+relu) (+residual). A,B bf16; C bf16 unless RES (fp32+res).
// 128x128x32 tile, 256 thr = 8 warps (2m x 4n), warp tile 64x32.
// As: [128 r][32 bf16] 64B rows, chunk swizzle c ^ ((r>>1)&3)
// Bs: [32 r][128 bf16] 256B rows, chunk swizzle c ^ (r&7), ldmatrix.trans
// ---------------------------------------------------------------------------
template<bool RELU, bool RES>
__global__ __launch_bounds__(256) void bgemm_kernel(
    const __nv_bfloat16* __restrict__ A, const __nv_bfloat16* __restrict__ B,
    const float* __restrict__ bias, const float* __restrict__ res,
    void* __restrict__ Cout, int M, int N, int K)
{
    __shared__ __align__(16) unsigned As[3][2048];   // 3 x 8KB
    __shared__ __align__(16) unsigned Bs[3][2048];   // 3 x 8KB

    const int tid = threadIdx.x, lane = tid & 31, wid = tid >> 5;
    const int wm = wid >> 2, wn = wid & 3;
    const int bm = blockIdx.y * 128, bn = blockIdx.x * 128;

    // g2s: A row = tid>>1, 2 chunks at (tid&1)*2; B k-row = tid>>3, 2 chunks at (tid&7)*2
    const int ar  = tid >> 1, ac0 = (tid & 1) * 2;
    const int br  = tid >> 3, bc0 = (tid & 7) * 2;
    const __nv_bfloat16* Ap = A + (size_t)(bm + ar) * K + ac0 * 8;
    const __nv_bfloat16* Bp = B + (size_t)br * N + bn + bc0 * 8;

    unsigned a_s[2], b_s[2];
    #pragma unroll
    for (int j = 0; j < 2; j++) {
        int ca = ac0 + j;
        a_s[j] = ar * 16 + ((ca ^ ((ar >> 1) & 3)) << 2);
        int cb = bc0 + j;
        b_s[j] = br * 64 + ((cb ^ (br & 7)) << 2);
    }

    const int ra0 = wm * 64 + (lane & 7) + ((lane >> 3) & 1) * 8;
    const int sA  = (ra0 >> 1) & 3;
    const int rb0 = (lane & 7) + ((lane >> 3) & 1) * 8;
    const int sB  = lane & 7;
    const int top = lane >> 4;

    float acc[4][4][4];
    #pragma unroll
    for (int i = 0; i < 4; i++)
        #pragma unroll
        for (int j = 0; j < 4; j++)
            #pragma unroll
            for (int k = 0; k < 4; k++) acc[i][j][k] = 0.f;

    const int nst = K >> 5;

    auto issue = [&](int buf, int k0) {
        #pragma unroll
        for (int j = 0; j < 2; j++)
            cpa16(sptr(&As[buf][a_s[j]]) , Ap + k0 + j * 8);
        #pragma unroll
        for (int j = 0; j < 2; j++)
            cpa16(sptr(&Bs[buf][b_s[j]]) , Bp + (size_t)k0 * N + j * 8);
    };

    issue(0, 0);  cp_commit();
    issue(1, 32); cp_commit();

    for (int st = 0; st < nst; st++) {
        cp_wait<1>();          // stage st resident (st+1 may be in flight)
        __syncthreads();       // all warps done computing st-1; data visible

        int nf = st + 2;
        if (nf < nst) issue(nf % 3, nf << 5);
        cp_commit();           // commit every iteration to keep group count aligned

        const int buf = st % 3;
        const unsigned abase = sptr(&As[buf][0]);
        const unsigned bbase = sptr(&Bs[buf][0]);
        #pragma unroll
        for (int s = 0; s < 2; s++) {
            unsigned af[4][4];
            #pragma unroll
            for (int mt = 0; mt < 4; mt++) {
                int row = ra0 + mt * 16;
                int c   = 2 * s + top;
                ldsm4(af[mt][0], af[mt][1], af[mt][2], af[mt][3],
                      abase + (row << 6) + ((c ^ sA) << 4));
            }
            unsigned bf[4][2];
            #pragma unroll
            for (int g = 0; g < 2; g++) {
                int row = s * 16 + rb0;
                int c   = wn * 4 + 2 * g + top;
                unsigned r0, r1, r2, r3;
                ldsm4t(r0, r1, r2, r3, bbase + (row << 8) + ((c ^ sB) << 4));
                bf[2*g][0] = r0; bf[2*g][1] = r1;
                bf[2*g+1][0] = r2; bf[2*g+1][1] = r3;
            }
            #pragma unroll
            for (int mt = 0; mt < 4; mt++)
                #pragma unroll
                for (int nt = 0; nt < 4; nt++)
                    mma_bf16(acc[mt][nt], af[mt][0], af[mt][1], af[mt][2],
                             af[mt][3], bf[nt][0], bf[nt][1]);
        }
    }

    // epilogue
    #pragma unroll
    for (int mt = 0; mt < 4; mt++) {
        #pragma unroll
        for (int nt = 0; nt < 4; nt++) {
            int row0 = bm + wm * 64 + mt * 16 + (lane >> 2);
            int col  = bn + wn * 32 + nt * 8 + (lane & 3) * 2;
            float bx = bias[col], by = bias[col + 1];
            #pragma unroll
            for (int half = 0; half < 2; half++) {
                int row = row0 + 8 * half;
                float v0 = acc[mt][nt][2 * half + 0] + bx;
                float v1 = acc[mt][nt][2 * half + 1] + by;
                if (RELU) { v0 = fmaxf(v0, 0.f); v1 = fmaxf(v1, 0.f); }
                if (RES) {
                    float* Cf = (float*)Cout;
                    const float2 rr = *(const float2*)&res[(size_t)row * N + col];
                    float2 ov; ov.x = v0 + rr.x; ov.y = v1 + rr.y;
                    *(float2*)&Cf[(size_t)row * N + col] = ov;
                } else {
                    __nv_bfloat16* Cb = (__nv_bfloat16*)Cout;
                    *(unsigned*)&Cb[(size_t)row * N + col] = pk(v0, v1);
                }
            }
        }
    }
}

// ---------------------------------------------------------------------------
// Flash attention, bf16 tensor cores, cp.async double-buffered K/V prefetch.
// Block = (b,h,64-query tile), 128 threads.
// ---------------------------------------------------------------------------
__global__ __launch_bounds__(128) void attn_kernel(const int* __restrict__ mask)
{
    __shared__ __align__(16) unsigned Qs[64 * 32];      // 8KB
    __shared__ __align__(16) unsigned Ks[2][64 * 32];   // 16KB
    __shared__ __align__(16) unsigned Vs[2][64 * 32];   // 16KB
    __shared__ float mb[2][64];

    const int tid = threadIdx.x, lane = tid & 31, w = tid >> 5;
    const int b = blockIdx.y >> 4, h = blockIdx.y & 15, qt = blockIdx.x;

    // g2s: row = tid>>1 (0..63), 4 chunks at (tid&1)*4
    const int gr = tid >> 1, gc0 = (tid & 1) * 4;
    unsigned soff[4];
    #pragma unroll
    for (int j = 0; j < 4; j++) {
        int c = gc0 + j;
        soff[j] = gr * 32 + ((c ^ (gr & 7)) << 2);
    }

    const __nv_bfloat16* Qg = g_q + (size_t)(b * SS + qt * 64 + gr) * DD + h * 64 + gc0 * 8;
    const __nv_bfloat16* Kg = g_k + (size_t)(b * SS + gr) * DD + h * 64 + gc0 * 8;
    const __nv_bfloat16* Vg = g_v + (size_t)(b * SS + gr) * DD + h * 64 + gc0 * 8;

    auto issueKV = [&](int buf, int kt) {
        const __nv_bfloat16* Kt = Kg + (size_t)(kt * 64) * DD;
        const __nv_bfloat16* Vt = Vg + (size_t)(kt * 64) * DD;
        #pragma unroll
        for (int j = 0; j < 4; j++) {
            cpa16(sptr(&Ks[buf][soff[j]]), Kt + j * 8);
            cpa16(sptr(&Vs[buf][soff[j]]), Vt + j * 8);
        }
    };

    // prologue: Q (group 0), KV tile 0 (group 1)
    #pragma unroll
    for (int j = 0; j < 4; j++) cpa16(sptr(&Qs[soff[j]]), Qg + j * 8);
    cp_commit();
    issueKV(0, 0);
    if (tid < 64) mb[0][tid] = mask[b * SS + tid] ? 0.f : -1e9f;
    cp_commit();

    cp_wait<1>();          // Q resident
    __syncthreads();

    // hoist Q fragments
    const int rq0 = w * 16 + (lane & 7) + ((lane >> 3) & 1) * 8;
    const int rk0 = (lane & 7) + ((lane >> 3) & 1) * 8;
    const int top = lane >> 4;
    const unsigned qb = sptr(Qs);
    unsigned qf[4][4];
    #pragma unroll
    for (int s = 0; s < 4; s++) {
        int c = 2 * s + top;
        ldsm4(qf[s][0], qf[s][1], qf[s][2], qf[s][3],
              qb + (rq0 << 7) + ((c ^ (rq0 & 7)) << 4));
    }

    float m0 = -1e30f, m1 = -1e30f, l0 = 0.f, l1 = 0.f;
    float oacc[8][4];
    #pragma unroll
    for (int j = 0; j < 8; j++)
        #pragma unroll
        for (int k = 0; k < 4; k++) oacc[j][k] = 0.f;

    for (int kt = 0; kt < SS / 64; kt++) {
        __syncthreads();                    // all warps done with buf (kt+1)&1's old data
        if (kt + 1 < SS / 64) {
            issueKV((kt + 1) & 1, kt + 1);
            if (tid < 64)
                mb[(kt + 1) & 1][tid] = mask[b * SS + (kt + 1) * 64 + tid] ? 0.f : -1e9f;
        }
        cp_commit();
        cp_wait<1>();                       // tile kt resident; kt+1 in flight
        __syncthreads();

        const unsigned kb = sptr(&Ks[kt & 1][0]);
        const unsigned vb = sptr(&Vs[kt & 1][0]);
        const float* mrow = mb[kt & 1];

        // ---- S = Q K^T ----
        float sacc[8][4];
        #pragma unroll
        for (int j = 0; j < 8; j++)
            #pragma unroll
            for (int k = 0; k < 4; k++) sacc[j][k] = 0.f;

        #pragma unroll
        for (int s = 0; s < 4; s++) {
            unsigned bf[8][2];
            #pragma unroll
            for (int g = 0; g < 4; g++) {
                int row = g * 16 + rk0;
                int c   = 2 * s + top;
                unsigned r0, r1, r2, r3;
                ldsm4(r0, r1, r2, r3, kb + (row << 7) + ((c ^ (lane & 7)) << 4));
                bf[2*g][0] = r0; bf[2*g][1] = r2;
                bf[2*g+1][0] = r1; bf[2*g+1][1] = r3;
            }
            #pragma unroll
            for (int j = 0; j < 8; j++)
                mma_bf16(sacc[j], qf[s][0], qf[s][1], qf[s][2], qf[s][3],
                         bf[j][0], bf[j][1]);
        }

        // ---- scale + mask + online softmax ----
        float mx0 = -1e30f, mx1 = -1e30f;
        #pragma unroll
        for (int j = 0; j < 8; j++) {
            float2 mj = *(const float2*)&mrow[j * 8 + (lane & 3) * 2];
            sacc[j][0] = sacc[j][0] * 0.125f + mj.x;
            sacc[j][1] = sacc[j][1] * 0.125f + mj.y;
            sacc[j][2] = sacc[j][2] * 0.125f + mj.x;
            sacc[j][3] = sacc[j][3] * 0.125f + mj.y;
            mx0 = fmaxf(mx0, fmaxf(sacc[j][0], sacc[j][1]));
            mx1 = fmaxf(mx1, fmaxf(sacc[j][2], sacc[j][3]));
        }
        mx0 = fmaxf(mx0, __shfl_xor_sync(0xffffffffu, mx0, 1, 4));
        mx0 = fmaxf(mx0, __shfl_xor_sync(0xffffffffu, mx0, 2, 4));
        mx1 = fmaxf(mx1, __shfl_xor_sync(0xffffffffu, mx1, 1, 4));
        mx1 = fmaxf(mx1, __shfl_xor_sync(0xffffffffu, mx1, 2, 4));

        float nm0 = fmaxf(m0, mx0), nm1 = fmaxf(m1, mx1);
        float al0 = __expf(m0 - nm0), al1 = __expf(m1 - nm1);
        m0 = nm0; m1 = nm1;

        float rs0 = 0.f, rs1 = 0.f;
        #pragma unroll
        for (int j = 0; j < 8; j++) {
            sacc[j][0] = __expf(sacc[j][0] - nm0);
            sacc[j][1] = __expf(sacc[j][1] - nm0);
            sacc[j][2] = __expf(sacc[j][2] - nm1);
            sacc[j][3] = __expf(sacc[j][3] - nm1);
            rs0 += sacc[j][0] + sacc[j][1];
            rs1 += sacc[j][2] + sacc[j][3];
        }
        rs0 += __shfl_xor_sync(0xffffffffu, rs0, 1, 4);
        rs0 += __shfl_xor_sync(0xffffffffu, rs0, 2, 4);
        rs1 += __shfl_xor_sync(0xffffffffu, rs1, 1, 4);
        rs1 += __shfl_xor_sync(0xffffffffu, rs1, 2, 4);
        l0 = l0 * al0 + rs0;
        l1 = l1 * al1 + rs1;

        #pragma unroll
        for (int j = 0; j < 8; j++) {
            oacc[j][0] *= al0; oacc[j][1] *= al0;
            oacc[j][2] *= al1; oacc[j][3] *= al1;
        }

        // ---- O += P V ----
        #pragma unroll
        for (int k4 = 0; k4 < 4; k4++) {
            unsigned pa0 = pk(sacc[2*k4][0],   sacc[2*k4][1]);
            unsigned pa1 = pk(sacc[2*k4][2],   sacc[2*k4][3]);
            unsigned pa2 = pk(sacc[2*k4+1][0], sacc[2*k4+1][1]);
            unsigned pa3 = pk(sacc[2*k4+1][2], sacc[2*k4+1][3]);
            #pragma unroll
            for (int g = 0; g < 4; g++) {
                int row = k4 * 16 + rk0;
                int c   = 2 * g + top;
                unsigned r0, r1, r2, r3;
                ldsm4t(r0, r1, r2, r3, vb + (row << 7) + ((c ^ (lane & 7)) << 4));
                mma_bf16(oacc[2*g],   pa0, pa1, pa2, pa3, r0, r1);
                mma_bf16(oacc[2*g+1], pa0, pa1, pa2, pa3, r2, r3);
            }
        }
    }

    // ---- write O (bf16) ----
    float i0 = 1.0f / l0, i1 = 1.0f / l1;
    int row0 = b * SS + qt * 64 + w * 16 + (lane >> 2);
    __nv_bfloat16* O0 = g_o + (size_t)row0 * DD + h * 64;
    __nv_bfloat16* O1 = O0 + (size_t)8 * DD;
    #pragma unroll
    for (int j = 0; j < 8; j++) {
        int d = j * 8 + (lane & 3) * 2;
        *(unsigned*)&O0[d] = pk(oacc[j][0] * i0, oacc[j][1] * i0);
        *(unsigned*)&O1[d] = pk(oacc[j][2] * i1, oacc[j][3] * i1);
    }
}

// ---------------------------------------------------------------------------
// Launch
// ---------------------------------------------------------------------------
extern "C" void kernel_launch(void* const* d_in, const int* in_sizes, int n_in,
                              void* d_out, int out_size)
{
    (void)in_sizes; (void)n_in; (void)out_size;
    const int*   tokens = (const int*)  d_in[0];
    const int*   mask   = (const int*)  d_in[1];
    const float* emb    = (const float*)d_in[2];
    const float* pe     = (const float*)d_in[3];
    const float* Wq     = (const float*)d_in[4];
    const float* bq     = (const float*)d_in[5];
    const float* Wk     = (const float*)d_in[6];
    const float* bk     = (const float*)d_in[7];
    const float* Wv     = (const float*)d_in[8];
    const float* bv     = (const float*)d_in[9];
    const float* Wo     = (const float*)d_in[10];
    const float* bo     = (const float*)d_in[11];
    const float* w1     = (const float*)d_in[12];
    const float* b1     = (const float*)d_in[13];
    const float* w2     = (const float*)d_in[14];
    const float* b2     = (const float*)d_in[15];
    const float* ln_a   = (const float*)d_in[16];
    const float* ln_b   = (const float*)d_in[17];
    const float* fa     = (const float*)d_in[18];
    const float* fb     = (const float*)d_in[19];
    float* out = (float*)d_out;

    float* px;
    __nv_bfloat16 *ph, *pq, *pk_, *pv, *po, *pmid;
    __nv_bfloat16 *wq, *wk, *wv, *wo, *pw1, *pw2;
    cudaGetSymbolAddress((void**)&px,   g_x);
    cudaGetSymbolAddress((void**)&ph,   g_h);
    cudaGetSymbolAddress((void**)&pq,   g_q);
    cudaGetSymbolAddress((void**)&pk_,  g_k);
    cudaGetSymbolAddress((void**)&pv,   g_v);
    cudaGetSymbolAddress((void**)&po,   g_o);
    cudaGetSymbolAddress((void**)&pmid, g_mid);
    cudaGetSymbolAddress((void**)&wq,   g_wq);
    cudaGetSymbolAddress((void**)&wk,   g_wk);
    cudaGetSymbolAddress((void**)&wv,   g_wv);
    cudaGetSymbolAddress((void**)&wo,   g_wo);
    cudaGetSymbolAddress((void**)&pw1,  g_w1);
    cudaGetSymbolAddress((void**)&pw2,  g_w2);

    const int nD = LL * DD * DD / 2048;   // 1536 blocks
    const int nF = LL * DD * FF / 2048;   // 6144 blocks
    cvt_kernel<<<nD, 256>>>(Wq, wq);
    cvt_kernel<<<nD, 256>>>(Wk, wk);
    cvt_kernel<<<nD, 256>>>(Wv, wv);
    cvt_kernel<<<nD, 256>>>(Wo, wo);
    cvt_kernel<<<nF, 256>>>(w1, pw1);
    cvt_kernel<<<nF, 256>>>(w2, pw2);

    embed_kernel<<<(MM * DD) / 256, 256>>>(tokens, emb, pe);

    dim3 gD(DD / 128, MM / 128);
    dim3 gF(FF / 128, MM / 128);

    for (int l = 0; l < LL; l++) {
        const float* lnA = ln_a + l * 2 * DD;
        const float* lnB = ln_b + l * 2 * DD;

        ln_kernel<true><<<MM, 256>>>(px, ph, lnA, lnB);
        bgemm_kernel<false, false><<<gD, 256>>>(ph, wq + (size_t)l * DD * DD,
                                                bq + l * DD, nullptr, pq, MM, DD, DD);
        bgemm_kernel<false, false><<<gD, 256>>>(ph, wk + (size_t)l * DD * DD,
                                                bk + l * DD, nullptr, pk_, MM, DD, DD);
        bgemm_kernel<false, false><<<gD, 256>>>(ph, wv + (size_t)l * DD * DD,
                                                bv + l * DD, nullptr, pv, MM, DD, DD);
        attn_kernel<<<dim3(SS / 64, BB * HH), 128>>>(mask);
        bgemm_kernel<false, true><<<gD, 256>>>(po, wo + (size_t)l * DD * DD,
                                               bo + l * DD, px, px, MM, DD, DD);

        ln_kernel<true><<<MM, 256>>>(px, ph, lnA + DD, lnB + DD);
        bgemm_kernel<true, false><<<gF, 256>>>(ph, pw1 + (size_t)l * DD * FF,
                                               b1 + l * FF, nullptr, pmid, MM, FF, DD);
        bgemm_kernel<false, true><<<gD, 256>>>(pmid, pw2 + (size_t)l * FF * DD,
                                               b2 + l * DD, px, px, MM, DD, FF);
    }

    ln_kernel<false><<<MM, 256>>>(px, out, fa, fb);
}